// round 16
// baseline (speedup 1.0000x reference)
#include <cuda_runtime.h>

// Problem constants (fixed by setup_inputs):
// B=16, C=1, H=W=128, WS=8, N = B*WS*WS = 1024 windows, mask all ones.
// Canvas per batch: 1024 x 1024. Output = [canvas (16.7M f32) | windows copy (16.7M f32)].

#define NW        1024
#define BATCH     16
#define WSZ       8
#define CELLS     (WSZ * WSZ)     // 64
#define HH        128
#define TILE_F4   (HH * HH / 4)   // 4096 float4 per window
#define ROW_F4    (HH / 4)        // 32 float4 per window row
#define CANV_ROW4 (1024 / 4)      // 256 float4 per canvas row
#define CANV_B4   (1024 * 1024 / 4)

#define RPG       4               // canvas rows per row-group
#define NRG       (HH / RPG)      // 32 row-groups per strip
#define NSTRIP    (BATCH * WSZ)   // 128 strips: (batch, ty)
#define GTHREADS  256             // 8 warps; warp w owns tile column tx=w

// ---------------------------------------------------------------------------
// Strip-decomposed fused kernel: grid (NRG, NSTRIP) x 256 threads.
// Block = 4 complete canvas rows x 1024 px of strip (b, ty). Warp w owns
// tile column tx = w (lanes cover cols [128w, 128w+128)).
//
// Why: all prior configs (occ 35-58%, MLP 4-8) plateau at ~4.35 TB/s with
// 512B-granule strided accesses. This layout makes every stream long-run
// contiguous at DRAM: per warp-window read = 2 KB contiguous (4 window rows),
// copy write = 2 KB contiguous, block canvas write = 16 KB contiguous
// (4 full 4 KB rows). 4x longer runs on all three streams.
//
// Binning: warp 0 does mask row sums + shfl scan -> batch csum; threads scan
// the <=64-window range of batch b for py==ty, binning ids by px into 8
// per-warp lists. After one barrier, warps proceed independently (no more
// block syncs; warp-level k imbalance is smoothed by the SM warp pool).
// Each window byte is still read exactly once chip-wide.
// ---------------------------------------------------------------------------
__global__ void __launch_bounds__(GTHREADS) hre_strip_kernel(
    const float4* __restrict__ win4,      // windows as float4
    const int*    __restrict__ positions, // [NW,2] i32
    const int4*   __restrict__ mask4,     // mask as int4
    float4* __restrict__ canvas4,         // output canvas (first half)
    float4* __restrict__ copy4)           // output windows copy (second half)
{
    const int rg    = blockIdx.x;         // row-group (fastest -> strip locality)
    const int strip = blockIdx.y;
    const int tid   = threadIdx.x;
    const int lane  = tid & 31;
    const int w     = tid >> 5;           // warp = tile column tx

    const int b  = strip >> 3;            // batch
    const int ty = strip & 7;             // tile row within batch

    __shared__ int csum_s[BATCH];
    __shared__ int cnt[WSZ];              // per-px counts
    __shared__ unsigned short list[WSZ * CELLS];

    // --- warp 0: per-batch mask sums + shfl inclusive scan -> csum ----------
    if (tid < 32) {
        int s = 0;
        if (lane < BATCH) {
            #pragma unroll
            for (int j = 0; j < CELLS / 4; ++j) {        // 16 independent int4
                const int4 m = mask4[lane * (CELLS / 4) + j];
                s += m.x + m.y + m.z + m.w;
            }
        }
        #pragma unroll
        for (int o = 1; o < BATCH; o <<= 1) {
            const int n = __shfl_up_sync(0xffffffffu, s, o);
            if (lane >= o) s += n;
        }
        if (lane < BATCH) csum_s[lane] = s;
    }
    if (tid < WSZ) cnt[tid] = 0;
    __syncthreads();

    // --- scan this batch's window range, bin by px ---------------------------
    const int win_start = (b == 0) ? 0 : csum_s[b - 1];
    const int win_n     = csum_s[b] - win_start;
    if (tid < win_n) {
        const int i  = win_start + tid;
        const int py = positions[2 * i + 0];
        const int px = positions[2 * i + 1];
        if (py == ty) {
            const int s = atomicAdd(&cnt[px], 1);
            list[px * CELLS + s] = (unsigned short)i;
        }
    }
    __syncthreads();                       // lists ready; no further block syncs
    const int k = cnt[w];

    // --- gather + fused copy (warp-independent) ------------------------------
    // This warp covers window rows [rg*RPG, rg*RPG+RPG) of its windows:
    // 4 rows x 32 f4 = 256 f4 contiguous starting at rg*RPG*ROW_F4.
    const int base0 = rg * RPG * ROW_F4 + lane;

    float4 acc[RPG];
    #pragma unroll
    for (int j = 0; j < RPG; ++j)
        acc[j] = make_float4(0.f, 0.f, 0.f, 0.f);

    for (int idx = 0; idx < k; ++idx) {
        const int wi = list[w * CELLS + idx];
        const float4* __restrict__ src = win4  + (size_t)wi * TILE_F4 + base0;
        float4*       __restrict__ dst = copy4 + (size_t)wi * TILE_F4 + base0;

        float4 v[RPG];
        #pragma unroll
        for (int j = 0; j < RPG; ++j)      // 4 loads, 2 KB contiguous per warp
            v[j] = __ldcs(src + j * ROW_F4);
        #pragma unroll
        for (int j = 0; j < RPG; ++j) {
            dst[j * ROW_F4] = v[j];        // copy: 2 KB contiguous per warp
            acc[j].x += v[j].x; acc[j].y += v[j].y;
            acc[j].z += v[j].z; acc[j].w += v[j].w;
        }
    }

    // --- normalized canvas writes: block writes 4 full 4 KB rows -------------
    const float inv = 1.0f / ((float)k + 1e-6f);
    const int row0  = ty * HH + rg * RPG;          // first canvas row
    const int cbase = b * CANV_B4 + row0 * CANV_ROW4 + w * ROW_F4 + lane;

    #pragma unroll
    for (int j = 0; j < RPG; ++j) {
        canvas4[cbase + j * CANV_ROW4] =
            make_float4(acc[j].x * inv, acc[j].y * inv,
                        acc[j].z * inv, acc[j].w * inv);
    }
}

// ---------------------------------------------------------------------------
extern "C" void kernel_launch(void* const* d_in, const int* in_sizes, int n_in,
                              void* d_out, int out_size)
{
    const float* windows   = (const float*)d_in[0];   // [NW,1,128,128] f32
    const int*   positions = (const int*)  d_in[1];   // [NW,2] i32
    const int*   mask      = (const int*)  d_in[2];   // [16,64] i32
    (void)in_sizes; (void)n_in; (void)out_size;

    float* out = (float*)d_out;
    float4* canvas4 = (float4*)out;
    float4* copy4   = (float4*)(out + (size_t)BATCH * 1024 * 1024);

    dim3 grid(NRG, NSTRIP);
    hre_strip_kernel<<<grid, GTHREADS>>>((const float4*)windows, positions,
                                         (const int4*)mask, canvas4, copy4);
}

// round 17
// speedup vs baseline: 1.0008x; 1.0008x over previous
#include <cuda_runtime.h>

// Problem constants (fixed by setup_inputs):
// B=16, C=1, H=W=128, WS=8, N = B*WS*WS = 1024 windows, mask all ones.
// Canvas per batch: 1024 x 1024. Output = [canvas (16.7M f32) | windows copy (16.7M f32)].

#define NW        1024
#define BATCH     16
#define WSZ       8
#define CELLS     (WSZ * WSZ)     // 64
#define NTILES    (BATCH * CELLS) // 1024
#define HH        128
#define TILE_F4   (HH * HH / 4)   // 4096 float4 per tile
#define CANV_ROW4 (1024 / 4)      // 256 float4 per canvas row
#define CANV_B4   (1024 * 1024 / 4)

#define NSEG      4
#define SEG_F4    (TILE_F4 / NSEG)   // 1024 float4 per segment
#define SEG_V8    (SEG_F4 / 2)       // 512 v8 (32-byte) chunks per segment
#define GTHREADS  256
#define JV8       (SEG_V8 / GTHREADS) // 2 v8 chunks per thread (64 B in flight)

// ---- sm_100a 256-bit global accesses --------------------------------------
__device__ __forceinline__ void ld_v8_ef(const float* p, float4& a, float4& b) {
    asm volatile("ld.global.L2::evict_first.v8.f32 {%0,%1,%2,%3,%4,%5,%6,%7}, [%8];"
        : "=f"(a.x), "=f"(a.y), "=f"(a.z), "=f"(a.w),
          "=f"(b.x), "=f"(b.y), "=f"(b.z), "=f"(b.w)
        : "l"(p));
}
__device__ __forceinline__ void st_v8(float* p, const float4& a, const float4& b) {
    asm volatile("st.global.v8.f32 [%0], {%1,%2,%3,%4,%5,%6,%7,%8};"
        :: "l"(p), "f"(a.x), "f"(a.y), "f"(a.z), "f"(a.w),
           "f"(b.x), "f"(b.y), "f"(b.z), "f"(b.w)
        : "memory");
}

// ---------------------------------------------------------------------------
// R10 structure (best measured: seg-major, NSEG=4, 256 thr, batch-local
// binning) with the data path widened to 256-bit accesses: each thread moves
// 2 x 32 B chunks per window (same 64 B in flight as R10's 4 x 16 B, but half
// the transactions -> 1 KB contiguous per warp per access). Targets the
// read/write turnaround overhead implicated by the 8-config ~4.3 TB/s
// plateau. Reads evict-first (read-once); stores write-back so dirty output
// lines can stay L2-resident across graph replays (measured ~45 MB saved).
// ---------------------------------------------------------------------------
__global__ void __launch_bounds__(GTHREADS) hre_fused_kernel(
    const float*  __restrict__ win,       // windows f32 base
    const int*    __restrict__ positions, // [NW,2] i32
    const int*    __restrict__ mask,      // [BATCH, CELLS] i32
    float* __restrict__ canvas,           // output canvas (first half)
    float* __restrict__ copy)             // output windows copy (second half)
{
    const int seg  = blockIdx.x;          // seg-major: consecutive bids share a tile
    const int tile = blockIdx.y;
    const int tid  = threadIdx.x;

    const int b    = tile >> 6;
    const int cell = tile & 63;
    const int ty   = cell >> 3;
    const int tx   = cell & 7;

    __shared__ int bsum[BATCH];
    __shared__ int list_cnt;
    __shared__ int win_start, win_n;
    __shared__ unsigned short list[CELLS];

    // --- batch sizes: 256 threads x 4 mask entries = 1024 = BATCH*CELLS ----
    if (tid < BATCH) bsum[tid] = 0;
    if (tid == 0) list_cnt = 0;
    __syncthreads();
    {
        int part = 0;
        #pragma unroll
        for (int j = 0; j < 4; ++j) part += mask[tid * 4 + j];
        atomicAdd(&bsum[tid >> 4], part);
    }
    __syncthreads();
    if (tid == 0) {
        int s = 0, st = 0;
        #pragma unroll
        for (int bb = 0; bb < BATCH; ++bb) {
            if (bb == b) st = s;
            s += bsum[bb];
            if (bb == b) { win_start = st; win_n = s - st; }
        }
    }
    __syncthreads();

    // --- scan only this batch's window range (<= 64 windows) ---------------
    for (int i = win_start + tid; i < win_start + win_n; i += GTHREADS) {
        const int py = positions[2 * i + 0];
        const int px = positions[2 * i + 1];
        if (py == ty && px == tx) {
            const int s = atomicAdd(&list_cnt, 1);
            list[s] = (unsigned short)i;
        }
    }
    __syncthreads();
    const int k = list_cnt;

    // --- gather + fused copy, 256-bit wide ----------------------------------
    // thread's v8 chunk j: index cj = j*GTHREADS + tid within segment;
    // float offset = (seg*SEG_F4 + 2*cj)*4  (32-byte aligned).
    float4 accA[JV8], accB[JV8];
    #pragma unroll
    for (int j = 0; j < JV8; ++j) {
        accA[j] = make_float4(0.f, 0.f, 0.f, 0.f);
        accB[j] = make_float4(0.f, 0.f, 0.f, 0.f);
    }

    const int fbase = (seg * SEG_F4 + 2 * tid) * 4;   // float index of chunk j=0

    for (int w = 0; w < k; ++w) {
        const int wi = list[w];
        const float* __restrict__ src = win  + (size_t)wi * (TILE_F4 * 4) + fbase;
        float*       __restrict__ dst = copy + (size_t)wi * (TILE_F4 * 4) + fbase;

        float4 vA[JV8], vB[JV8];
        #pragma unroll
        for (int j = 0; j < JV8; ++j)        // 2 independent 32 B loads
            ld_v8_ef(src + j * (GTHREADS * 8), vA[j], vB[j]);
        #pragma unroll
        for (int j = 0; j < JV8; ++j) {
            st_v8(dst + j * (GTHREADS * 8), vA[j], vB[j]);   // fused passthrough
            accA[j].x += vA[j].x; accA[j].y += vA[j].y;
            accA[j].z += vA[j].z; accA[j].w += vA[j].w;
            accB[j].x += vB[j].x; accB[j].y += vB[j].y;
            accB[j].z += vB[j].z; accB[j].w += vB[j].w;
        }
    }

    // --- normalized canvas writes (256-bit) ---------------------------------
    const float inv = 1.0f / ((float)k + 1e-6f);
    // canvas float4 base of this tile
    const int cbase4 = b * CANV_B4 + ty * HH * CANV_ROW4 + tx * (HH / 4);

    #pragma unroll
    for (int j = 0; j < JV8; ++j) {
        const int p8 = j * GTHREADS + tid + seg * SEG_V8;   // v8 index in tile
        const int r  = p8 >> 4;                 // 16 v8 per 128-px tile row
        const int c8 = p8 & 15;
        float* cp = canvas + (size_t)(cbase4 + r * CANV_ROW4 + c8 * 2) * 4;
        const float4 oA = make_float4(accA[j].x * inv, accA[j].y * inv,
                                      accA[j].z * inv, accA[j].w * inv);
        const float4 oB = make_float4(accB[j].x * inv, accB[j].y * inv,
                                      accB[j].z * inv, accB[j].w * inv);
        st_v8(cp, oA, oB);
    }
}

// ---------------------------------------------------------------------------
extern "C" void kernel_launch(void* const* d_in, const int* in_sizes, int n_in,
                              void* d_out, int out_size)
{
    const float* windows   = (const float*)d_in[0];   // [NW,1,128,128] f32
    const int*   positions = (const int*)  d_in[1];   // [NW,2] i32
    const int*   mask      = (const int*)  d_in[2];   // [16,64] i32
    (void)in_sizes; (void)n_in; (void)out_size;

    float* out = (float*)d_out;
    float* canvas = out;                                   // first 16.7M floats
    float* copy   = out + (size_t)BATCH * 1024 * 1024;     // windows copy

    dim3 grid(NSEG, NTILES);              // seg-major
    hre_fused_kernel<<<grid, GTHREADS>>>(windows, positions, mask, canvas, copy);
}